// round 12
// baseline (speedup 1.0000x reference)
#include <cuda_runtime.h>

#define C_S 384
#define C_Z 128
#define MAX_N 2048
#define NSM 148
#define MAIN_BLKS (NSM * 3)   // 444: one resident wave at 3 blocks/SM
#define CHUNK 8               // batches per atomic pop (8 x 4KB = 32KB)

// device globals (allocation-free rule)
__device__ float g_si[MAX_N];
__device__ float g_sj[MAX_N];
__device__ unsigned g_next;            // dynamic chunk counter
__device__ unsigned g_exit;            // blocks exited (for reset)
__device__ volatile unsigned g_ready;  // si/sj rows published

// ---------------------------------------------------------------------------
// Single fused kernel.
// Blocks [0, preBlocks): si/sj precompute (scheduled first -> resident in
//   wave 1 -> publish is deadlock-free), then exit.
// Blocks [preBlocks, ...): persistent z-stream with dynamic chunk popping.
//   First loads issue BEFORE the readiness spin, so the precompute hides
//   under the DRAM ramp. Dynamic popping keeps the chip-wide address window
//   dense (the property that beat contiguous ranges in R9) and self-balances
//   the late-starting blocks.
// ---------------------------------------------------------------------------
__device__ __forceinline__ void load_batch(const float4* __restrict__ z4,
                                           int batch, int lane, float4 v[8]) {
    size_t row0 = (size_t)batch * (8 * (C_Z / 4));
#pragma unroll
    for (int i = 0; i < 8; i++)
        v[i] = __ldg(z4 + row0 + i * (C_Z / 4) + lane);
}

__device__ __forceinline__ void process_batch(const float4 v[8], float4 wz,
                                              float b0, int batch,
                                              int lane, int N,
                                              float* __restrict__ out) {
    float a0 = v[0].x * wz.x + v[0].y * wz.y + v[0].z * wz.z + v[0].w * wz.w;
    float a1 = v[1].x * wz.x + v[1].y * wz.y + v[1].z * wz.z + v[1].w * wz.w;
    float a2 = v[2].x * wz.x + v[2].y * wz.y + v[2].z * wz.z + v[2].w * wz.w;
    float a3 = v[3].x * wz.x + v[3].y * wz.y + v[3].z * wz.z + v[3].w * wz.w;
    float a4 = v[4].x * wz.x + v[4].y * wz.y + v[4].z * wz.z + v[4].w * wz.w;
    float a5 = v[5].x * wz.x + v[5].y * wz.y + v[5].z * wz.z + v[5].w * wz.w;
    float a6 = v[6].x * wz.x + v[6].y * wz.y + v[6].z * wz.z + v[6].w * wz.w;
    float a7 = v[7].x * wz.x + v[7].y * wz.y + v[7].z * wz.z + v[7].w * wz.w;

    // Select-and-exchange multi-value reduction (9 shfls total).
    bool s0b = (lane & 1);
    float t0 = s0b ? a1 : a0;
    float t1 = s0b ? a3 : a2;
    float t2 = s0b ? a5 : a4;
    float t3 = s0b ? a7 : a6;
    t0 += __shfl_xor_sync(0xFFFFFFFFu, s0b ? a0 : a1, 1);
    t1 += __shfl_xor_sync(0xFFFFFFFFu, s0b ? a2 : a3, 1);
    t2 += __shfl_xor_sync(0xFFFFFFFFu, s0b ? a4 : a5, 1);
    t3 += __shfl_xor_sync(0xFFFFFFFFu, s0b ? a6 : a7, 1);
    bool s1b = (lane & 2);
    float u0 = s1b ? t1 : t0;
    float u1 = s1b ? t3 : t2;
    u0 += __shfl_xor_sync(0xFFFFFFFFu, s1b ? t0 : t1, 2);
    u1 += __shfl_xor_sync(0xFFFFFFFFu, s1b ? t2 : t3, 2);
    bool s2b = (lane & 4);
    float r = s2b ? u1 : u0;
    r += __shfl_xor_sync(0xFFFFFFFFu, s2b ? u0 : u1, 4);
    r += __shfl_xor_sync(0xFFFFFFFFu, r, 8);
    r += __shfl_xor_sync(0xFFFFFFFFu, r, 16);
    // lane l holds full sum for row (l & 7)

    if (lane < 8) {
        int base = batch * 8;
        int n  = base / N;            // N=1024 -> shift
        int m0 = base - n * N;
        out[(size_t)base + lane] = r + g_si[n] + b0 + g_sj[m0 + lane];
    }
}

__global__ __launch_bounds__(256, 3) void contact_fused_kernel(
    const float* __restrict__ s,
    const float* __restrict__ z,
    const float* __restrict__ W,
    const float* __restrict__ bias,
    float* __restrict__ out,
    int N, int preBlocks) {
    int lane = threadIdx.x & 31;
    int wid  = threadIdx.x >> 5;

    if ((int)blockIdx.x < preBlocks) {
        // ---- Precompute role: one warp per row ----
        int row = blockIdx.x * 8 + wid;
        if (row < N) {
            const float4* s4  = (const float4*)(s + (size_t)row * C_S);
            const float4* wi4 = (const float4*)W;
            const float4* wj4 = (const float4*)(W + C_S);
            float ai = 0.f, aj = 0.f;
#pragma unroll
            for (int i = 0; i < 3; i++) {
                int k = lane + 32 * i;
                float4 v  = __ldg(s4 + k);
                float4 wi = __ldg(wi4 + k);
                float4 wj = __ldg(wj4 + k);
                ai += v.x * wi.x + v.y * wi.y + v.z * wi.z + v.w * wi.w;
                aj += v.x * wj.x + v.y * wj.y + v.z * wj.z + v.w * wj.w;
            }
#pragma unroll
            for (int off = 16; off; off >>= 1) {
                ai += __shfl_xor_sync(0xFFFFFFFFu, ai, off);
                aj += __shfl_xor_sync(0xFFFFFFFFu, aj, off);
            }
            if (lane == 0) {
                g_si[row] = ai;
                g_sj[row] = aj;
                __threadfence();
                atomicAdd((unsigned*)&g_ready, 1u);
            }
        }
    } else {
        // ---- Main stream role: dynamic chunk popping ----
        int nb = (N * N) / 8;  // total batches

        const float4* wz4 = (const float4*)(W + 2 * C_S);
        float4 wz = __ldg(wz4 + lane);
        float b0  = __ldg(bias);
        const float4* z4 = (const float4*)z;

        // pop: chunk index from global counter, broadcast to warp
        unsigned c;
        if (lane == 0) c = atomicAdd(&g_next, 1u);
        c = __shfl_sync(0xFFFFFFFFu, c, 0);
        int batch = (int)c * CHUNK;
        int bend  = batch + CHUNK; if (bend > nb) bend = nb;

        if (batch < nb) {
            // prefetch next chunk index (hides pop latency at boundary)
            unsigned cn;
            if (lane == 0) cn = atomicAdd(&g_next, 1u);
            cn = __shfl_sync(0xFFFFFFFFu, cn, 0);

            float4 va[8], vb[8];
            load_batch(z4, batch, lane, va);  // loads in flight first...

            // ...then wait for si/sj (usually already done / hidden by ramp)
            if (lane == 0) {
                while (g_ready < (unsigned)N) { }
            }
            __syncwarp();
            __threadfence();  // acquire ordering for g_si/g_sj reads

            // advance helper semantics inlined: next batch or next chunk
            int nxt;
            for (;;) {
                // compute successor of 'batch'
                nxt = batch + 1;
                if (nxt >= bend) {
                    nxt = (int)cn * CHUNK;
                    if (nxt < nb) {
                        bend = nxt + CHUNK; if (bend > nb) bend = nb;
                        if (lane == 0) cn = atomicAdd(&g_next, 1u);
                        cn = __shfl_sync(0xFFFFFFFFu, cn, 0);
                    } else {
                        nxt = nb;  // no more work
                    }
                }
                if (nxt >= nb) { process_batch(va, wz, b0, batch, lane, N, out); break; }
                load_batch(z4, nxt, lane, vb);
                process_batch(va, wz, b0, batch, lane, N, out);
                batch = nxt;

                nxt = batch + 1;
                if (nxt >= bend) {
                    nxt = (int)cn * CHUNK;
                    if (nxt < nb) {
                        bend = nxt + CHUNK; if (bend > nb) bend = nb;
                        if (lane == 0) cn = atomicAdd(&g_next, 1u);
                        cn = __shfl_sync(0xFFFFFFFFu, cn, 0);
                    } else {
                        nxt = nb;
                    }
                }
                if (nxt >= nb) { process_batch(vb, wz, b0, batch, lane, N, out); break; }
                load_batch(z4, nxt, lane, va);
                process_batch(vb, wz, b0, batch, lane, N, out);
                batch = nxt;
            }
        }
    }

    // ---- Reset counters for next graph replay: last block out ----
    __syncthreads();
    if (threadIdx.x == 0) {
        unsigned done = atomicAdd(&g_exit, 1u);
        if (done == gridDim.x - 1) {
            g_exit = 0;
            g_next = 0;
            *(unsigned*)&g_ready = 0;
            __threadfence();
        }
    }
}

extern "C" void kernel_launch(void* const* d_in, const int* in_sizes, int n_in,
                              void* d_out, int out_size) {
    const float* s    = (const float*)d_in[0];   // (1, N, 384)
    const float* z    = (const float*)d_in[1];   // (1, N, N, 128)
    const float* W    = (const float*)d_in[2];   // (1, 896)
    const float* bias = (const float*)d_in[3];   // (1,)
    float* out = (float*)d_out;                  // (1, N, N, 1)

    int N = in_sizes[0] / C_S;                   // B=1

    int preBlocks = (N * 32 + 255) / 256;        // 128 for N=1024
    int blocks = preBlocks + MAIN_BLKS;          // 572
    contact_fused_kernel<<<blocks, 256>>>(s, z, W, bias, out, N, preBlocks);
}

// round 13
// speedup vs baseline: 1.1768x; 1.1768x over previous
#include <cuda_runtime.h>

#define C_S 384
#define C_Z 128
#define MAX_N 2048

// scratch for per-row projections (allocation-free rule: device globals)
__device__ float g_si[MAX_N];
__device__ float g_sj[MAX_N];

// ---------------------------------------------------------------------------
// Kernel 1: si[n] = dot(s[n,:], W[0:384]), sj[n] = dot(s[n,:], W[384:768])
// One warp per row, float4-vectorized (3x LDG.128 of s per lane).
// ---------------------------------------------------------------------------
__global__ void precompute_sisj_kernel(const float* __restrict__ s,
                                       const float* __restrict__ W,
                                       int N) {
    int warp = (blockIdx.x * blockDim.x + threadIdx.x) >> 5;
    int lane = threadIdx.x & 31;
    if (warp >= N) return;
    const float4* s4  = (const float4*)(s + (size_t)warp * C_S);  // 96 float4
    const float4* wi4 = (const float4*)W;
    const float4* wj4 = (const float4*)(W + C_S);
    float ai = 0.f, aj = 0.f;
#pragma unroll
    for (int i = 0; i < 3; i++) {
        int k = lane + 32 * i;
        float4 v  = __ldg(s4 + k);
        float4 wi = __ldg(wi4 + k);
        float4 wj = __ldg(wj4 + k);
        ai += v.x * wi.x + v.y * wi.y + v.z * wi.z + v.w * wi.w;
        aj += v.x * wj.x + v.y * wj.y + v.z * wj.z + v.w * wj.w;
    }
#pragma unroll
    for (int off = 16; off; off >>= 1) {
        ai += __shfl_xor_sync(0xFFFFFFFFu, ai, off);
        aj += __shfl_xor_sync(0xFFFFFFFFu, aj, off);
    }
    if (lane == 0) {
        g_si[warp] = ai;
        g_sj[warp] = aj;
    }
}

// ---------------------------------------------------------------------------
// Kernel 2 (R4 champion config — best measured wall: 84.0us, 84.2% DRAM):
// out[n*N + m] = g_si[n] + g_sj[m] + dot(z[n,m,:], Wz) + b
// One warp per 8 consecutive m (same n), non-persistent grid of 16384 blocks.
// Each lane loads one float4 of each 512-byte z-row -> fully coalesced,
// MLP=8 independent LDG.128 per warp. Select-and-exchange reduction: 8
// accumulators merged with 9 shfls; afterwards lane l holds the full sum
// for row (l & 7), so lanes 0..7 do a coalesced 32B store.
// ---------------------------------------------------------------------------
__global__ __launch_bounds__(256) void contact_main_kernel(
    const float* __restrict__ z,
    const float* __restrict__ W,
    const float* __restrict__ bias,
    float* __restrict__ out,
    int N) {
    int warp = (blockIdx.x * blockDim.x + threadIdx.x) >> 5;
    int lane = threadIdx.x & 31;

    long long base = (long long)warp * 8;
    long long total = (long long)N * (long long)N;
    if (base >= total) return;

    int n  = (int)(base / N);
    int m0 = (int)(base - (long long)n * N);   // N % 8 == 0 -> all 8 share n

    // Wz = W[768:896], resident in L1/L2 after first touch
    const float4* wz4 = (const float4*)(W + 2 * C_S);
    float4 wz = __ldg(wz4 + lane);
    float b0  = __ldg(bias);

    const float4* z4 = (const float4*)z;
    size_t row0 = ((size_t)n * N + m0) * (C_Z / 4);  // float4 index of row m0

    float a0, a1, a2, a3, a4, a5, a6, a7;
    {
        float4 v0 = __ldg(z4 + row0 + 0 * (C_Z / 4) + lane);
        float4 v1 = __ldg(z4 + row0 + 1 * (C_Z / 4) + lane);
        float4 v2 = __ldg(z4 + row0 + 2 * (C_Z / 4) + lane);
        float4 v3 = __ldg(z4 + row0 + 3 * (C_Z / 4) + lane);
        float4 v4 = __ldg(z4 + row0 + 4 * (C_Z / 4) + lane);
        float4 v5 = __ldg(z4 + row0 + 5 * (C_Z / 4) + lane);
        float4 v6 = __ldg(z4 + row0 + 6 * (C_Z / 4) + lane);
        float4 v7 = __ldg(z4 + row0 + 7 * (C_Z / 4) + lane);
        a0 = v0.x * wz.x + v0.y * wz.y + v0.z * wz.z + v0.w * wz.w;
        a1 = v1.x * wz.x + v1.y * wz.y + v1.z * wz.z + v1.w * wz.w;
        a2 = v2.x * wz.x + v2.y * wz.y + v2.z * wz.z + v2.w * wz.w;
        a3 = v3.x * wz.x + v3.y * wz.y + v3.z * wz.z + v3.w * wz.w;
        a4 = v4.x * wz.x + v4.y * wz.y + v4.z * wz.z + v4.w * wz.w;
        a5 = v5.x * wz.x + v5.y * wz.y + v5.z * wz.z + v5.w * wz.w;
        a6 = v6.x * wz.x + v6.y * wz.y + v6.z * wz.z + v6.w * wz.w;
        a7 = v7.x * wz.x + v7.y * wz.y + v7.z * wz.z + v7.w * wz.w;
    }

    // Select-and-exchange multi-value reduction (9 shfls total).
    bool s0b = (lane & 1);
    float t0 = s0b ? a1 : a0;
    float t1 = s0b ? a3 : a2;
    float t2 = s0b ? a5 : a4;
    float t3 = s0b ? a7 : a6;
    t0 += __shfl_xor_sync(0xFFFFFFFFu, s0b ? a0 : a1, 1);
    t1 += __shfl_xor_sync(0xFFFFFFFFu, s0b ? a2 : a3, 1);
    t2 += __shfl_xor_sync(0xFFFFFFFFu, s0b ? a4 : a5, 1);
    t3 += __shfl_xor_sync(0xFFFFFFFFu, s0b ? a6 : a7, 1);
    bool s1b = (lane & 2);
    float u0 = s1b ? t1 : t0;
    float u1 = s1b ? t3 : t2;
    u0 += __shfl_xor_sync(0xFFFFFFFFu, s1b ? t0 : t1, 2);
    u1 += __shfl_xor_sync(0xFFFFFFFFu, s1b ? t2 : t3, 2);
    bool s2b = (lane & 4);
    float r = s2b ? u1 : u0;
    r += __shfl_xor_sync(0xFFFFFFFFu, s2b ? u0 : u1, 4);
    r += __shfl_xor_sync(0xFFFFFFFFu, r, 8);
    r += __shfl_xor_sync(0xFFFFFFFFu, r, 16);
    // lane l now holds the full 32-lane sum for row index (l & 7)

    if (lane < 8) {
        float sn = g_si[n] + b0;
        out[base + lane] = r + sn + g_sj[m0 + lane];
    }
}

extern "C" void kernel_launch(void* const* d_in, const int* in_sizes, int n_in,
                              void* d_out, int out_size) {
    const float* s    = (const float*)d_in[0];   // (1, N, 384)
    const float* z    = (const float*)d_in[1];   // (1, N, N, 128)
    const float* W    = (const float*)d_in[2];   // (1, 896)
    const float* bias = (const float*)d_in[3];   // (1,)
    float* out = (float*)d_out;                  // (1, N, N, 1)

    int N = in_sizes[0] / C_S;                   // B=1

    // Kernel 1: one warp per row
    {
        int warps = N;
        int threads = 256;
        int blocks = (warps * 32 + threads - 1) / threads;
        precompute_sisj_kernel<<<blocks, threads>>>(s, W, N);
    }

    // Kernel 2: one warp per 8 outputs, non-persistent (R4 champion)
    {
        long long total = (long long)N * (long long)N;
        long long warps = (total + 7) / 8;
        int threads = 256;
        long long blocks = (warps * 32 + threads - 1) / threads;
        contact_main_kernel<<<(unsigned)blocks, threads>>>(z, W, bias, out, N);
    }
}